// round 12
// baseline (speedup 1.0000x reference)
#include <cuda_runtime.h>
#include <cuda_bf16.h>
#include <math.h>
#include <stdint.h>

#define N_NODES 8192
#define KSEL 32
#define ROWS_PER_CTA 32
#define CAP 256
#define COMPACT_HI 128

__device__ float g_Af[N_NODES * 128];                 // [v1 | -v2] fp32
__device__ float g_Bf[N_NODES * 128];                 // [v2 |  v1] fp32
__device__ __nv_bfloat16 g_Abf[N_NODES * 128];        // hi(A)
__device__ __nv_bfloat16 g_Bbf[N_NODES * 128];        // hi(B)

__device__ __forceinline__ uint32_t smem_u32(const void* p) {
    uint32_t a;
    asm("{ .reg .u64 t; cvta.to.shared.u64 t, %1; cvt.u32.u64 %0, t; }" : "=r"(a) : "l"(p));
    return a;
}
__device__ __forceinline__ uint32_t sw128(uint32_t byte) {
    return byte ^ ((byte >> 3) & 0x70);
}
__device__ __forceinline__ void ldmatrix_x4(uint32_t& r0, uint32_t& r1,
                                            uint32_t& r2, uint32_t& r3, uint32_t addr) {
    asm volatile("ldmatrix.sync.aligned.m8n8.x4.shared.b16 {%0,%1,%2,%3}, [%4];"
                 : "=r"(r0), "=r"(r1), "=r"(r2), "=r"(r3) : "r"(addr));
}
__device__ __forceinline__ void mma_bf16(float* c, const uint32_t* a, uint32_t b0, uint32_t b1) {
    asm volatile("mma.sync.aligned.m16n8k16.row.col.f32.bf16.bf16.f32 "
                 "{%0,%1,%2,%3}, {%4,%5,%6,%7}, {%8,%9}, {%0,%1,%2,%3};"
                 : "+f"(c[0]), "+f"(c[1]), "+f"(c[2]), "+f"(c[3])
                 : "r"(a[0]), "r"(a[1]), "r"(a[2]), "r"(a[3]), "r"(b0), "r"(b1));
}

// ---------------------------------------------------------------------------
// Kernel 1: prep — hi-only bf16 pack (unchanged)
// ---------------------------------------------------------------------------
__global__ void __launch_bounds__(128) prep_kernel(
    const float* __restrict__ emb,
    const float* __restrict__ W1, const float* __restrict__ b1,
    const float* __restrict__ W2, const float* __restrict__ b2)
{
    __shared__ float sW[2][64][65];
    __shared__ float sb[2][64];
    __shared__ float semb[16][64];

    const int tid = threadIdx.x;
    for (int i = tid; i < 64 * 64; i += 128) {
        int r = i >> 6, k = i & 63;
        sW[0][r][k] = W1[i];
        sW[1][r][k] = W2[i];
    }
    if (tid < 64) { sb[0][tid] = b1[tid]; sb[1][tid] = b2[tid]; }

    const int nodeBase = blockIdx.x * 16;
    for (int i = tid; i < 16 * 64; i += 128)
        semb[i >> 6][i & 63] = emb[(size_t)(nodeBase + (i >> 6)) * 64 + (i & 63)];
    __syncthreads();

    const int h = tid >> 6;
    const int r = tid & 63;
    for (int n = 0; n < 16; n++) {
        float acc = sb[h][r];
#pragma unroll
        for (int k = 0; k < 64; k++)
            acc = fmaf(semb[n][k], sW[h][r][k], acc);
        float v = 0.5f * acc * (1.0f + erff(acc * 0.70710678118654752f));
        const int node = nodeBase + n;

        if (h == 0) {
            g_Af[node * 128 + r]      = v;
            g_Bf[node * 128 + 64 + r] = v;
            __nv_bfloat16 hi = __float2bfloat16_rn(v);
            g_Abf[node * 128 + r]      = hi;
            g_Bbf[node * 128 + 64 + r] = hi;
        } else {
            float av = -v;
            g_Af[node * 128 + 64 + r] = av;
            g_Bf[node * 128 + r]      = v;
            g_Abf[node * 128 + 64 + r] = __float2bfloat16_rn(av);
            g_Bbf[node * 128 + r]      = __float2bfloat16_rn(v);
        }
    }
}

// ---------------------------------------------------------------------------
// Fused kernel: 256 CTAs x 256 threads, 32-row strips, 128-col tiles.
// 2 CTAs/SM; B single-buffered + register prefetch. (R11 w/ address fix:
// smem stores use GENERIC pointers; sbase only feeds ldmatrix.)
// ---------------------------------------------------------------------------
#define OFF_A    0            // 2 chunks x 4KB = 8KB
#define OFF_B    8192         // 32KB stage (2 k-chunk halves of 16KB)
#define OFF_CS   40960        // 32 * 256 * 4 = 32768
#define OFF_CJ   73728        // 32 * 256 * 2 = 16384
#define OFF_THR  90112
#define OFF_CNT  90240
#define SMEM_FUSED 90368

__global__ void __launch_bounds__(256, 2) fused_kernel(
    const float* __restrict__ noise, float* __restrict__ out)
{
    extern __shared__ char smem[];
    const uint32_t sbase = smem_u32(smem);
    float*    cs  = (float*)(smem + OFF_CS);
    uint16_t* cj  = (uint16_t*)(smem + OFF_CJ);
    float*    thr = (float*)(smem + OFF_THR);
    int*      cnt = (int*)(smem + OFF_CNT);

    const int tid = threadIdx.x;
    const int lane = tid & 31;
    const int warp = tid >> 5;           // 0..7
    const int warpN = warp & 3;          // 32-col slice
    const int warpM = warp >> 2;         // 16-row slice
    const int rowBase = blockIdx.x * ROWS_PER_CTA;

    // zero output slab
    {
        float4* o4 = (float4*)(out + (size_t)rowBase * N_NODES);
        const float4 z = make_float4(0.f, 0.f, 0.f, 0.f);
        for (int i = tid; i < ROWS_PER_CTA * N_NODES / 4; i += 256) o4[i] = z;
    }
    if (tid < 32) { thr[tid] = -1.0f; cnt[tid] = 0; }

    // load A strip: 32 rows x 256B, 2 chunks of 4KB, SW128
    {
        const char* gA = (const char*)g_Abf;
        for (int idx = tid; idx < 512; idx += 256) {
            int row = idx >> 4, rem = idx & 15;
            int c = rem >> 3, q = rem & 7;
            uint4 v = *(const uint4*)(gA + (size_t)(rowBase + row) * 256 + c * 128 + q * 16);
            *(uint4*)(smem + OFF_A + c * 4096 + sw128(row * 128 + q * 16)) = v;
        }
    }

    const int laneRow = lane & 15;
    const int laneK = lane >> 4;
    const int lrBase = warpM * 16 + (lane >> 2);

    // B staging: thread owns node (tid>>1) within tile, k-half (tid&1)
    const char* gB = (const char*)g_Bbf;
    const int bNode = tid >> 1;          // 0..127
    const int bHalf = tid & 1;           // k-chunk
    char* stDst[8];                      // GENERIC pointers (fix for R11 crash)
#pragma unroll
    for (int q = 0; q < 8; q++)
        stDst[q] = smem + OFF_B + bHalf * 16384 + sw128(bNode * 128 + q * 16);

    // prefetch B(0) into registers
    uint4 breg[8];
    {
        const char* src = gB + (size_t)(bNode) * 256 + bHalf * 128;
#pragma unroll
        for (int q = 0; q < 8; q++) breg[q] = *(const uint4*)(src + q * 16);
    }

    for (int t = 0; t < 64; t++) {
        const int colBase = t * 128;

        // stage B(t) into smem
#pragma unroll
        for (int q = 0; q < 8; q++) *(uint4*)stDst[q] = breg[q];
        __syncthreads();

        // prefetch B(t+1) — latency hidden by this tile's compute
        if (t < 63) {
            const char* src = gB + (size_t)((t + 1) * 128 + bNode) * 256 + bHalf * 128;
#pragma unroll
            for (int q = 0; q < 8; q++) breg[q] = *(const uint4*)(src + q * 16);
        }

        float acc[4][4];
#pragma unroll
        for (int n8 = 0; n8 < 4; n8++)
#pragma unroll
            for (int q = 0; q < 4; q++) acc[n8][q] = 0.0f;

#pragma unroll
        for (int ks = 0; ks < 8; ks++) {
            const int c = ks >> 2, kk = ks & 3;
            const uint32_t aBuf = sbase + OFF_A + c * 4096;
            const uint32_t bBuf = sbase + OFF_B + c * 16384;
            uint32_t afr[4];
            ldmatrix_x4(afr[0], afr[1], afr[2], afr[3],
                        aBuf + sw128((warpM * 16 + laneRow) * 128 + kk * 32 + laneK * 16));
#pragma unroll
            for (int nq = 0; nq < 2; nq++) {
                uint32_t r0, r1, r2, r3;
                ldmatrix_x4(r0, r1, r2, r3,
                            bBuf + sw128((warpN * 32 + nq * 16 + laneRow) * 128 + kk * 32 + laneK * 16));
                mma_bf16(acc[nq * 2],     afr, r0, r2);
                mma_bf16(acc[nq * 2 + 1], afr, r1, r3);
            }
        }

        // ---- append: single phase (128 cols => cnt <= 128+128 = CAP) ----
        {
            const float th0 = thr[lrBase];
            const float th1 = thr[lrBase + 8];
#pragma unroll
            for (int n8 = 0; n8 < 4; n8++) {
                const int col = colBase + warpN * 32 + n8 * 8 + (lane & 3) * 2;
                float s0 = fmaxf(acc[n8][0], 0.f);
                float s1 = fmaxf(acc[n8][1], 0.f);
                float s2 = fmaxf(acc[n8][2], 0.f);
                float s3 = fmaxf(acc[n8][3], 0.f);
                if (s0 > th0) {
                    int p = atomicAdd(&cnt[lrBase], 1);
                    if (p < CAP) { cs[lrBase * CAP + p] = s0; cj[lrBase * CAP + p] = (uint16_t)col; }
                }
                if (s1 > th0) {
                    int p = atomicAdd(&cnt[lrBase], 1);
                    if (p < CAP) { cs[lrBase * CAP + p] = s1; cj[lrBase * CAP + p] = (uint16_t)(col + 1); }
                }
                if (s2 > th1) {
                    int p = atomicAdd(&cnt[lrBase + 8], 1);
                    if (p < CAP) { cs[(lrBase + 8) * CAP + p] = s2; cj[(lrBase + 8) * CAP + p] = (uint16_t)col; }
                }
                if (s3 > th1) {
                    int p = atomicAdd(&cnt[lrBase + 8], 1);
                    if (p < CAP) { cs[(lrBase + 8) * CAP + p] = s3; cj[(lrBase + 8) * CAP + p] = (uint16_t)(col + 1); }
                }
            }
        }
        __syncthreads();

        // ---- compaction: warp w owns rows w*4 .. w*4+3 ----
#pragma unroll 1
        for (int rr = 0; rr < 4; rr++) {
            const int r = warp * 4 + rr;
            int n = cnt[r];
            if (n > COMPACT_HI) {
                if (n > CAP) n = CAP;
                unsigned sbits[8];
#pragma unroll
                for (int q = 0; q < 8; q++) {
                    int i = lane + q * 32;
                    sbits[q] = (i < n) ? __float_as_uint(cs[r * CAP + i]) : 0u;
                }
                unsigned lo = 0, hi = 0x7f800000u, T = 0;
                for (int it = 0; it < 32; it++) {
                    unsigned mid = lo + ((hi - lo) >> 1);
                    int c = 0;
#pragma unroll
                    for (int q = 0; q < 8; q++)
                        c += __popc(__ballot_sync(0xffffffffu, sbits[q] > mid));
                    if (c > 96) lo = mid + 1;
                    else if (c < 48) { if (mid == 0) { T = 0; break; } hi = mid - 1; }
                    else { T = mid; break; }
                    if (lo > hi) { T = hi; break; }
                }
                // margin = 0.01 (noise) + 0.025 (bf16 adj error); zero-clamped
                const float fT = fmaxf(__uint_as_float(T) - 0.035f, 1e-30f);
                int base = 0;
#pragma unroll
                for (int q = 0; q < 8; q++) {
                    int i = lane + q * 32;
                    bool keep = (i < n) && (__uint_as_float(sbits[q]) > fT);
                    unsigned m = __ballot_sync(0xffffffffu, keep);
                    float v; uint16_t jv;
                    if (keep) { v = cs[r * CAP + i]; jv = cj[r * CAP + i]; }
                    int pos = base + __popc(m & ((1u << lane) - 1u));
                    if (keep) { cs[r * CAP + pos] = v; cj[r * CAP + pos] = jv; }
                    base += __popc(m);
                }
                if (lane == 0) { cnt[r] = base; thr[r] = fT; }
            }
            __syncwarp();
        }
        __syncthreads();
    }

    // ------ tail: exact fp32 rescore + exact top-32 per row ------
    {
        float4* saf4 = (float4*)(smem + OFF_B);    // 32 rows x 128 fp32 = 16KB
        for (int idx = tid; idx < 32 * 32; idx += 256) {
            int row = idx >> 5, k4 = idx & 31;
            saf4[idx] = *(const float4*)(g_Af + (size_t)(rowBase + row) * 128 + k4 * 4);
        }
    }
    __syncthreads();

    const float4* saf = (const float4*)(smem + OFF_B);
    int* win = (int*)(smem + OFF_A) + warp * 64;

#pragma unroll 1
    for (int rr = 0; rr < 4; rr++) {
        const int r = warp * 4 + rr;
        const int rowG = rowBase + r;
        int n = cnt[r];
        if (n > CAP) n = CAP;

        for (int i = lane; i < n; i += 32) {
            const int j = (int)cj[r * CAP + i];
            float d = 0.f;
#pragma unroll
            for (int k4 = 0; k4 < 32; k4++) {
                float4 a = saf[r * 32 + k4];
                float4 b = *(const float4*)(g_Bf + (size_t)j * 128 + k4 * 4);
                d = fmaf(a.x, b.x, fmaf(a.y, b.y, fmaf(a.z, b.z, fmaf(a.w, b.w, d))));
            }
            float adjv = fmaxf(d, 0.f);
            float sc = __fadd_rn(adjv, __fmul_rn(0.01f, __ldg(noise + (size_t)rowG * N_NODES + j)));
            cs[r * CAP + i] = sc;
        }
        __syncwarp();

        unsigned sbits[8];
#pragma unroll
        for (int q = 0; q < 8; q++) {
            int i = lane + q * 32;
            sbits[q] = (i < n) ? __float_as_uint(cs[r * CAP + i]) : 0u;
        }
        unsigned lo = 0, hi = 0x7f800000u, T = 0;
        for (int it = 0; it < 32; it++) {
            unsigned mid = lo + ((hi - lo) >> 1);
            int c = 0;
#pragma unroll
            for (int q = 0; q < 8; q++)
                c += __popc(__ballot_sync(0xffffffffu, sbits[q] > mid));
            if (c > 48) lo = mid + 1;
            else if (c < 32) { if (mid == 0) { T = 0; break; } hi = mid - 1; }
            else { T = mid; break; }
            if (lo > hi) { T = hi; break; }
        }

        int wn = 0;
#pragma unroll
        for (int q = 0; q < 8; q++) {
            int i = lane + q * 32;
            bool keep = (i < n) && (sbits[q] > T);
            unsigned m = __ballot_sync(0xffffffffu, keep);
            int pos = wn + __popc(m & ((1u << lane) - 1u));
            if (keep && pos < 64) win[pos] = i;
            wn += __popc(m);
        }
        if (wn > 64) wn = 64;
        __syncwarp();

        while (wn > KSEL) {
            unsigned long long bk = ~0ull; int bp = -1;
            for (int p = lane; p < wn; p += 32) {
                int i = win[p];
                unsigned long long key =
                    ((unsigned long long)__float_as_uint(cs[r * CAP + i]) << 32)
                  | (unsigned)(0xFFFFu - cj[r * CAP + i]);
                if (key < bk) { bk = key; bp = p; }
            }
#pragma unroll
            for (int off = 16; off > 0; off >>= 1) {
                unsigned long long ok = __shfl_down_sync(0xffffffffu, bk, off);
                int op = __shfl_down_sync(0xffffffffu, bp, off);
                if (ok < bk) { bk = ok; bp = op; }
            }
            bp = __shfl_sync(0xffffffffu, bp, 0);
            if (lane == 0) win[bp] = win[wn - 1];
            __syncwarp();
            wn--;
        }

        if (lane < wn) {
            const int j = (int)cj[r * CAP + win[lane]];
            float d = 0.f;
#pragma unroll
            for (int k4 = 0; k4 < 32; k4++) {
                float4 a = saf[r * 32 + k4];
                float4 b = *(const float4*)(g_Bf + (size_t)j * 128 + k4 * 4);
                d = fmaf(a.x, b.x, fmaf(a.y, b.y, fmaf(a.z, b.z, fmaf(a.w, b.w, d))));
            }
            out[(size_t)rowG * N_NODES + j] = fmaxf(d, 0.f);
        }
        __syncwarp();
    }
}

// ---------------------------------------------------------------------------
extern "C" void kernel_launch(void* const* d_in, const int* in_sizes, int n_in,
                              void* d_out, int out_size)
{
    const float* emb   = (const float*)d_in[0];
    const float* noise = (const float*)d_in[1];
    const float* W1    = (const float*)d_in[2];
    const float* b1    = (const float*)d_in[3];
    const float* W2    = (const float*)d_in[4];
    const float* b2    = (const float*)d_in[5];
    float* out = (float*)d_out;

    cudaFuncSetAttribute(fused_kernel, cudaFuncAttributeMaxDynamicSharedMemorySize, SMEM_FUSED);

    prep_kernel<<<N_NODES / 16, 128>>>(emb, W1, b1, W2, b2);
    fused_kernel<<<N_NODES / ROWS_PER_CTA, 256, SMEM_FUSED>>>(noise, out);
}